// round 9
// baseline (speedup 1.0000x reference)
#include <cuda_runtime.h>
#include <cstdint>

#define W      30
#define TT     4096
#define FF     128
#define NS     (TT - W + 1)        // 4067 window starts
#define SEG    150                 // outputs per CTA (5 groups of 30)
#define NG     5
#define CH     30                  // rows per chunk == W (static smem offsets)
#define NCHUNK 6                   // 180 staged rows >= 179 needed
#define CHF    (CH * FF)           // floats per chunk = 3840
#define SMEM_BYTES (NCHUNK * CHF * 4)   // 92160
#define EPSF   1e-4f

__device__ __forceinline__ void cp16(uint32_t saddr, const void* gaddr) {
    asm volatile("cp.async.cg.shared.global [%0], [%1], 16;" :: "r"(saddr), "l"(gaddr));
}
__device__ __forceinline__ void cp_commit() {
    asm volatile("cp.async.commit_group;");
}
template <int N>
__device__ __forceinline__ void cp_wait() {
    asm volatile("cp.async.wait_group %0;" :: "n"(N));
}

// One group of 30 outputs. sg = chunk g base (+f), sg1 = chunk g+1 base (+f),
// op = output row base (+f). Returns updated (s, s2).
__device__ __noinline__ float2 group30(const float* __restrict__ sg,
                                       const float* __restrict__ sg1,
                                       float* __restrict__ op,
                                       float s, float s2)
{
#pragma unroll
    for (int u = 0; u < W; ++u) {
        // nv row (local) = u + 29: chunk g offset 29 for u==0, else chunk g+1 offset u-1
        const float nv = (u == 0) ? sg[29 * FF] : sg1[(u - 1) * FF];

        const float ss  = s + nv;
        const float ss2 = fmaf(nv, nv, s2);

        const float mean   = ss  * (1.0f / W);
        const float meansq = ss2 * (1.0f / W);
        float var = fmaxf(fmaf(-mean, mean, meansq), 0.0f);

        float stdv;
        asm("sqrt.approx.f32 %0, %1;" : "=f"(stdv) : "f"(var));
        const float r = __fdividef(nv - mean, stdv + EPSF);

        __stcs(op + (size_t)u * FF, r);

        const float ov = sg[u * FF];       // row leaving the window (smem)
        s  = ss  - ov;
        s2 = fmaf(-ov, ov, ss2);
    }
    return make_float2(s, s2);
}

__global__ __launch_bounds__(FF)
void ts_zscore_kernel(const float* __restrict__ x, float* __restrict__ out)
{
    extern __shared__ float sm[];
    const int f = threadIdx.x;
    const int b = blockIdx.x;
    int k0 = blockIdx.y * SEG;
    if (k0 > NS - SEG) k0 = NS - SEG;     // tail block overlaps prior (same values)

    const uint32_t sbase = (uint32_t)__cvta_generic_to_shared(sm);
    const float* __restrict__ xb = x + (size_t)b * TT * FF;

    // Issue ALL 6 chunk copies up front (92 KB in flight per CTA).
    // Chunk c = rows k0+c*30 .. k0+c*30+29 (512 B/row). 960 16-byte units
    // per chunk, strided across 128 threads (7 full + 1 predicated round).
#pragma unroll
    for (int c = 0; c < NCHUNK; ++c) {
#pragma unroll
        for (int i = 0; i < 8; ++i) {
            const int idx = threadIdx.x + i * FF;       // 16B-unit index
            if (i < 7 || idx < CH * 32) {               // 960 units per chunk
                int grow = k0 + c * CH + (idx >> 5);    // global row
                if (grow > TT - 1) grow = TT - 1;       // clamp: row never consumed
                const float* g = xb + (size_t)grow * FF + ((idx & 31) << 2);
                cp16(sbase + (uint32_t)((c * CHF + idx * 4) * 4), g);
            }
        }
        cp_commit();
    }

    float* __restrict__ op = out + ((size_t)b * NS + k0) * FF + f;

    // Prime s,s2 with local rows 0..28 (chunk 0).
    cp_wait<5>(); __syncthreads();
    float s = 0.0f, s2 = 0.0f;
#pragma unroll
    for (int i = 0; i < W - 1; ++i) {
        const float v = sm[i * FF + f];
        s += v;
        s2 = fmaf(v, v, s2);
    }

    float2 st = make_float2(s, s2);
    cp_wait<4>(); __syncthreads();
    st = group30(sm + 0 * CHF + f, sm + 1 * CHF + f, op + (size_t)0 * W * FF, st.x, st.y);
    cp_wait<3>(); __syncthreads();
    st = group30(sm + 1 * CHF + f, sm + 2 * CHF + f, op + (size_t)1 * W * FF, st.x, st.y);
    cp_wait<2>(); __syncthreads();
    st = group30(sm + 2 * CHF + f, sm + 3 * CHF + f, op + (size_t)2 * W * FF, st.x, st.y);
    cp_wait<1>(); __syncthreads();
    st = group30(sm + 3 * CHF + f, sm + 4 * CHF + f, op + (size_t)3 * W * FF, st.x, st.y);
    cp_wait<0>(); __syncthreads();
    st = group30(sm + 4 * CHF + f, sm + 5 * CHF + f, op + (size_t)4 * W * FF, st.x, st.y);
}

extern "C" void kernel_launch(void* const* d_in, const int* in_sizes, int n_in,
                              void* d_out, int out_size)
{
    (void)n_in; (void)out_size;
    const float* x = (const float*)d_in[0];
    float* out = (float*)d_out;

    cudaFuncSetAttribute(ts_zscore_kernel,
                         cudaFuncAttributeMaxDynamicSharedMemorySize, SMEM_BYTES);

    const int B = in_sizes[0] / (TT * FF);   // 64 for this problem
    dim3 grid(B, (NS + SEG - 1) / SEG);      // (64, 28)
    ts_zscore_kernel<<<grid, FF, SMEM_BYTES>>>(x, out);
}

// round 10
// speedup vs baseline: 1.0468x; 1.0468x over previous
#include <cuda_runtime.h>
#include <cstdint>

#define W      30
#define TT     4096
#define FF     128
#define NS     (TT - W + 1)        // 4067 window starts
#define SEG    90                  // outputs per CTA (3 groups of 30)
#define NG     3
#define CH     30                  // rows per chunk == W (static smem offsets)
#define NCHUNK 4                   // 120 staged rows >= 119 needed
#define CHF    (CH * FF)           // floats per chunk = 3840
#define SMEM_BYTES (NCHUNK * CHF * 4)   // 61440 -> 3 CTAs/SM
#define EPSF   1e-4f

__device__ __forceinline__ void cp16(uint32_t saddr, const void* gaddr) {
    asm volatile("cp.async.cg.shared.global [%0], [%1], 16;" :: "r"(saddr), "l"(gaddr));
}
__device__ __forceinline__ void cp_commit() {
    asm volatile("cp.async.commit_group;");
}
template <int N>
__device__ __forceinline__ void cp_wait() {
    asm volatile("cp.async.wait_group %0;" :: "n"(N));
}

// One group of 30 outputs. sg = chunk g base (+f), sg1 = chunk g+1 base (+f),
// op = output row base (+f). Returns updated (s, s2).
__device__ __noinline__ float2 group30(const float* __restrict__ sg,
                                       const float* __restrict__ sg1,
                                       float* __restrict__ op,
                                       float s, float s2)
{
#pragma unroll
    for (int u = 0; u < W; ++u) {
        // nv row (local) = u + 29: chunk g row 29 for u==0 (compile-time),
        // else chunk g+1 row u-1.
        const float nv = (u == 0) ? sg[29 * FF] : sg1[(u - 1) * FF];

        const float ss  = s + nv;
        const float ss2 = fmaf(nv, nv, s2);

        const float mean   = ss  * (1.0f / W);
        const float meansq = ss2 * (1.0f / W);
        float var = fmaxf(fmaf(-mean, mean, meansq), 1e-12f);

        // 1/(std+eps) ~= rs*(1-eps*rs), rs = 1/sqrt(var). rel err ~eps^2/var.
        float rs;
        asm("rsqrt.approx.f32 %0, %1;" : "=f"(rs) : "f"(var));
        const float r = (nv - mean) * rs * fmaf(-EPSF, rs, 1.0f);

        __stcs(op + (size_t)u * FF, r);

        const float ov = sg[u * FF];       // row leaving the window (smem)
        s  = ss  - ov;
        s2 = fmaf(-ov, ov, ss2);
    }
    return make_float2(s, s2);
}

__global__ __launch_bounds__(FF)
void ts_zscore_kernel(const float* __restrict__ x, float* __restrict__ out)
{
    extern __shared__ float sm[];
    const int f = threadIdx.x;
    const int b = blockIdx.x;
    int k0 = blockIdx.y * SEG;
    if (k0 > NS - SEG) k0 = NS - SEG;     // tail block overlaps prior (same values)

    const uint32_t sbase = (uint32_t)__cvta_generic_to_shared(sm);
    const float* __restrict__ xb = x + (size_t)b * TT * FF;

    // Issue ALL 4 chunk copies up front (61 KB in flight per CTA).
    // Chunk c = rows k0+c*30 .. k0+c*30+29 (512 B/row) = 960 16-byte units.
#pragma unroll
    for (int c = 0; c < NCHUNK; ++c) {
#pragma unroll
        for (int i = 0; i < 8; ++i) {
            const int idx = threadIdx.x + i * FF;       // 16B-unit index
            if (i < 7 || idx < CH * 32) {               // 960 units per chunk
                int grow = k0 + c * CH + (idx >> 5);    // global row
                if (grow > TT - 1) grow = TT - 1;       // clamp: row never consumed
                const float* g = xb + (size_t)grow * FF + ((idx & 31) << 2);
                cp16(sbase + (uint32_t)((c * CHF + idx * 4) * 4), g);
            }
        }
        cp_commit();
    }

    float* __restrict__ op = out + ((size_t)b * NS + k0) * FF + f;

    // Prime s,s2 with local rows 0..28 (chunk 0).
    cp_wait<3>(); __syncthreads();
    float s = 0.0f, s2 = 0.0f;
#pragma unroll
    for (int i = 0; i < W - 1; ++i) {
        const float v = sm[i * FF + f];
        s += v;
        s2 = fmaf(v, v, s2);
    }

    float2 st = make_float2(s, s2);
    cp_wait<2>(); __syncthreads();
    st = group30(sm + 0 * CHF + f, sm + 1 * CHF + f, op + (size_t)0 * W * FF, st.x, st.y);
    cp_wait<1>(); __syncthreads();
    st = group30(sm + 1 * CHF + f, sm + 2 * CHF + f, op + (size_t)1 * W * FF, st.x, st.y);
    cp_wait<0>(); __syncthreads();
    st = group30(sm + 2 * CHF + f, sm + 3 * CHF + f, op + (size_t)2 * W * FF, st.x, st.y);
}

extern "C" void kernel_launch(void* const* d_in, const int* in_sizes, int n_in,
                              void* d_out, int out_size)
{
    (void)n_in; (void)out_size;
    const float* x = (const float*)d_in[0];
    float* out = (float*)d_out;

    cudaFuncSetAttribute(ts_zscore_kernel,
                         cudaFuncAttributeMaxDynamicSharedMemorySize, SMEM_BYTES);

    const int B = in_sizes[0] / (TT * FF);   // 64 for this problem
    dim3 grid(B, (NS + SEG - 1) / SEG);      // (64, 46)
    ts_zscore_kernel<<<grid, FF, SMEM_BYTES>>>(x, out);
}

// round 11
// speedup vs baseline: 1.0475x; 1.0007x over previous
#include <cuda_runtime.h>
#include <cstdint>

#define W      30
#define TT     4096
#define FF     128
#define NS     (TT - W + 1)        // 4067 window starts
#define SEG    60                  // outputs per CTA (2 halves of 30)
#define ROWS   (SEG + W)           // 90 staged rows (last one may clamp; unused)
#define UNITS  (ROWS * 32)         // 2880 16-byte units to stage
#define SMEM_BYTES (ROWS * FF * 4) // 46080 -> 4 CTAs/SM
#define EPSF   1e-4f

__device__ __forceinline__ void cp16(uint32_t saddr, const void* gaddr) {
    asm volatile("cp.async.cg.shared.global [%0], [%1], 16;" :: "r"(saddr), "l"(gaddr));
}
__device__ __forceinline__ void cp_commit() {
    asm volatile("cp.async.commit_group;");
}
template <int N>
__device__ __forceinline__ void cp_wait() {
    asm volatile("cp.async.wait_group %0;" :: "n"(N));
}

__global__ __launch_bounds__(256)
void ts_zscore_kernel(const float* __restrict__ x, float* __restrict__ out)
{
    extern __shared__ float sm[];
    const int f   = threadIdx.x;        // feature 0..127
    const int h   = threadIdx.y;        // half 0..1 (outputs [h*30, h*30+30))
    const int tid = threadIdx.y * FF + threadIdx.x;
    const int b   = blockIdx.x;

    int k0 = blockIdx.y * SEG;
    if (k0 > NS - SEG) k0 = NS - SEG;   // tail block overlaps prior (same values)

    const uint32_t sbase = (uint32_t)__cvta_generic_to_shared(sm);
    const float* __restrict__ xb = x + (size_t)b * TT * FF;

    // Stage 90 rows (k0 .. k0+89) in one shot: 2880 16B units over 256 threads.
    // Row k0+89 can exceed the tensor by one row (k0 max = 4007) — clamp; that
    // row is never consumed by compute (max consumed local row = 88).
#pragma unroll
    for (int i = 0; i < 12; ++i) {
        const int idx = tid + i * 256;
        if (i < 11 || idx < UNITS) {
            int grow = k0 + (idx >> 5);
            if (grow > TT - 1) grow = TT - 1;
            const float* g = xb + (size_t)grow * FF + ((idx & 31) << 2);
            cp16(sbase + (uint32_t)idx * 16u, g);
        }
    }
    cp_commit();

    // Per-half bases (half h works on local rows h*30 .. h*30+59).
    const float* __restrict__ sg = sm + (size_t)(h * W) * FF + f;
    float* __restrict__ op = out + ((size_t)b * NS + k0 + h * W) * FF + f;

    cp_wait<0>();
    __syncthreads();

    // Prime s,s2 with local rows 0..28 of this half.
    float s = 0.0f, s2 = 0.0f;
#pragma unroll
    for (int i = 0; i < W - 1; ++i) {
        const float v = sg[i * FF];
        s += v;
        s2 = fmaf(v, v, s2);
    }

#pragma unroll
    for (int u = 0; u < W; ++u) {
        const float nv = sg[(u + W - 1) * FF];   // row entering the window

        const float ss  = s + nv;
        const float ss2 = fmaf(nv, nv, s2);

        const float mean   = ss  * (1.0f / W);
        const float meansq = ss2 * (1.0f / W);
        float var = fmaxf(fmaf(-mean, mean, meansq), 1e-12f);

        // 1/(std+eps) ~= rs*(1-eps*rs), rs = rsqrt(var); rel err ~ eps^2/var.
        float rs;
        asm("rsqrt.approx.f32 %0, %1;" : "=f"(rs) : "f"(var));
        const float r = (nv - mean) * rs * fmaf(-EPSF, rs, 1.0f);

        __stcs(op + (size_t)u * FF, r);

        const float ov = sg[u * FF];             // row leaving the window
        s  = ss  - ov;
        s2 = fmaf(-ov, ov, ss2);
    }
}

extern "C" void kernel_launch(void* const* d_in, const int* in_sizes, int n_in,
                              void* d_out, int out_size)
{
    (void)n_in; (void)out_size;
    const float* x = (const float*)d_in[0];
    float* out = (float*)d_out;

    cudaFuncSetAttribute(ts_zscore_kernel,
                         cudaFuncAttributeMaxDynamicSharedMemorySize, SMEM_BYTES);

    const int B = in_sizes[0] / (TT * FF);   // 64 for this problem
    dim3 block(FF, 2);                        // 256 threads
    dim3 grid(B, (NS + SEG - 1) / SEG);       // (64, 68)
    ts_zscore_kernel<<<grid, block, SMEM_BYTES>>>(x, out);
}